// round 15
// baseline (speedup 1.0000x reference)
#include <cuda_runtime.h>
#include <cuda_fp16.h>
#include <cstring>

#define DD 64
#define NMAX 100000
#define EMAX 1200000

// Portable bit-casts
__device__ __forceinline__ unsigned h2_to_u32(__half2 h) { unsigned u; memcpy(&u, &h, 4); return u; }
__device__ __forceinline__ __half2 u32_to_h2(unsigned u) { __half2 h; memcpy(&h, &u, 4); return h; }

// Scratch (allocation-free rule: __device__ globals). 16B-aligned.
__device__ __align__(16) float  g_deg[NMAX];
__device__ __align__(16) float  g_dis[NMAX];
__device__ __align__(16) int    g_cnt[NMAX];
__device__ __align__(16) int    g_row[NMAX + 1];
__device__ __align__(16) int    g_cur[NMAX];
__device__ __align__(16) float2 g_pair[EMAX];       // (src as int bits, weight), bucketed by dst
__device__ __align__(16) __half g_hs [NMAX * DD];   // fp16: dis*(X@W1)
__device__ __align__(16) __half g_hs2[NMAX * DD];   // fp16: dis*(x1@W2)
__device__ __align__(16) float  g_x1 [NMAX * DD];   // layer-1 output (fp32)

// ---------------------------------------------------------------------------
// init: cnt = 0, deg = 1 (self-loop weight)
__global__ void init_kernel(int n) {
    int i = blockIdx.x * blockDim.x + threadIdx.x;
    if (i < n) { g_cnt[i] = 0; g_deg[i] = 1.0f; }
}

// count in-degree + weighted degree.  edge_index is INT32: src = ei[e], dst = ei[E+e].
__global__ void count_kernel(const int* __restrict__ ei,
                             const float* __restrict__ ew, int E) {
    int e = blockIdx.x * blockDim.x + threadIdx.x;
    if (e < E) {
        int d = ei[E + e];
        atomicAdd(&g_cnt[d], 1);
        atomicAdd(&g_deg[d], ew[e]);
    }
}

// single-block exclusive scan of g_cnt -> g_row, g_cur; fused: dis = rsqrt(deg)
__global__ __launch_bounds__(1024) void scan_dis_kernel(int n) {
    __shared__ int ssum[1024];
    int t = threadIdx.x;
    int chunk = (n + 1023) >> 10;
    int beg = t * chunk;
    int end = min(n, beg + chunk);
    int s = 0;
    for (int i = beg; i < end; i++) s += g_cnt[i];
    ssum[t] = s;
    __syncthreads();
    if (t == 0) {
        int acc = 0;
        for (int i = 0; i < 1024; i++) { int v = ssum[i]; ssum[i] = acc; acc += v; }
        g_row[n] = acc;
    }
    __syncthreads();
    int acc = ssum[t];
    for (int i = beg; i < end; i++) {
        int c = g_cnt[i];
        g_row[i] = acc;
        g_cur[i] = acc;
        acc += c;
        g_dis[i] = rsqrtf(g_deg[i]);   // deg >= 1 (self-loop)
    }
}

// bucket edges by dst: g_pair[slot] = (src, w)
__global__ void fill_kernel(const int* __restrict__ ei,
                            const float* __restrict__ ew, int E) {
    int e = blockIdx.x * blockDim.x + threadIdx.x;
    if (e < E) {
        int s = ei[e];
        int d = ei[E + e];
        int p = atomicAdd(&g_cur[d], 1);
        g_pair[p] = make_float2(__int_as_float(s), ew[e]);
    }
}

// ---------------------------------------------------------------------------
// 8-floats accumulate helper: acc += w * (8 fp16 values in a uint4)
__device__ __forceinline__ void fma8(float acc[8], float w, uint4 v) {
    float2 a0 = __half22float2(u32_to_h2(v.x));
    float2 a1 = __half22float2(u32_to_h2(v.y));
    float2 a2 = __half22float2(u32_to_h2(v.z));
    float2 a3 = __half22float2(u32_to_h2(v.w));
    acc[0] = fmaf(w, a0.x, acc[0]); acc[1] = fmaf(w, a0.y, acc[1]);
    acc[2] = fmaf(w, a1.x, acc[2]); acc[3] = fmaf(w, a1.y, acc[3]);
    acc[4] = fmaf(w, a2.x, acc[4]); acc[5] = fmaf(w, a2.y, acc[5]);
    acc[6] = fmaf(w, a3.x, acc[6]); acc[7] = fmaf(w, a3.y, acc[7]);
}

// Per-thread gather core: 8 lanes per node, lane q owns 8 fp16 columns (16B).
// out = relu(dis*acc + b) for columns [8q, 8q+8).  Edge loop unrolled x2.
__device__ __forceinline__ void gather_node8(const __half* __restrict__ hsrc,
                                             int d, int q, const float* __restrict__ b,
                                             float out[8]) {
    const uint4* __restrict__ hs4 = (const uint4*)hsrc;   // row stride 8 (64 halves / 8)
    float acc[8];
    {
        uint4 self = hs4[(size_t)d * 8 + q];
        float2 a0 = __half22float2(u32_to_h2(self.x));
        float2 a1 = __half22float2(u32_to_h2(self.y));
        float2 a2 = __half22float2(u32_to_h2(self.z));
        float2 a3 = __half22float2(u32_to_h2(self.w));
        acc[0] = a0.x; acc[1] = a0.y; acc[2] = a1.x; acc[3] = a1.y;
        acc[4] = a2.x; acc[5] = a2.y; acc[6] = a3.x; acc[7] = a3.y;
    }

    int beg = g_row[d];
    int end = g_row[d + 1];

    int i = beg;
    for (; i + 2 <= end; i += 2) {
        float2 p0 = g_pair[i];
        float2 p1 = g_pair[i + 1];
        uint4 v0 = hs4[(size_t)__float_as_int(p0.x) * 8 + q];
        uint4 v1 = hs4[(size_t)__float_as_int(p1.x) * 8 + q];
        fma8(acc, p0.y, v0);
        fma8(acc, p1.y, v1);
    }
    if (i < end) {
        float2 p0 = g_pair[i];
        uint4 v0 = hs4[(size_t)__float_as_int(p0.x) * 8 + q];
        fma8(acc, p0.y, v0);
    }

    float ds = g_dis[d];
    float4 b0 = ((const float4*)b)[2 * q];
    float4 b1 = ((const float4*)b)[2 * q + 1];
    out[0] = fmaxf(fmaf(ds, acc[0], b0.x), 0.f);
    out[1] = fmaxf(fmaf(ds, acc[1], b0.y), 0.f);
    out[2] = fmaxf(fmaf(ds, acc[2], b0.z), 0.f);
    out[3] = fmaxf(fmaf(ds, acc[3], b0.w), 0.f);
    out[4] = fmaxf(fmaf(ds, acc[4], b1.x), 0.f);
    out[5] = fmaxf(fmaf(ds, acc[5], b1.y), 0.f);
    out[6] = fmaxf(fmaf(ds, acc[6], b1.z), 0.f);
    out[7] = fmaxf(fmaf(ds, acc[7], b1.w), 0.f);
}

// ---------------------------------------------------------------------------
// GEMM layer 1: g_hs = fp16( dis[row] * (X @ W1) ).  R10-exact.
__global__ __launch_bounds__(256) void gemm_hs_kernel(
    const float* __restrict__ X, const float* __restrict__ W, int n)
{
    __shared__ float sW[DD * DD];
    __shared__ float sX[DD * DD];

    int t = threadIdx.x;
    int row0 = blockIdx.x * 64;

    {
        float4* sW4 = (float4*)sW;
        const float4* W4 = (const float4*)W;
        #pragma unroll
        for (int i = 0; i < 4; i++) sW4[t + i * 256] = W4[t + i * 256];
    }
    {
        float4* sX4 = (float4*)sX;
        const float4* X4 = (const float4*)X;
        if (row0 + 64 <= n) {
            #pragma unroll
            for (int i = 0; i < 4; i++) sX4[t + i * 256] = X4[(size_t)row0 * 16 + t + i * 256];
        } else {
            #pragma unroll
            for (int i = 0; i < 4; i++) {
                int idx = t + i * 256;
                int r = idx >> 4;
                float4 v = make_float4(0.f, 0.f, 0.f, 0.f);
                if (row0 + r < n) v = X4[(size_t)row0 * 16 + idx];
                sX4[idx] = v;
            }
        }
    }
    __syncthreads();

    int rg = (t >> 4) * 4;
    int c0 = (t & 15) * 4;

    float a[4][4];
    #pragma unroll
    for (int i = 0; i < 4; i++)
        #pragma unroll
        for (int j = 0; j < 4; j++) a[i][j] = 0.f;

    #pragma unroll 16
    for (int k = 0; k < 64; k++) {
        float4 wv = *(const float4*)(sW + k * 64 + c0);
        #pragma unroll
        for (int i = 0; i < 4; i++) {
            float xv = sX[(rg + i) * 64 + k];
            a[i][0] = fmaf(xv, wv.x, a[i][0]);
            a[i][1] = fmaf(xv, wv.y, a[i][1]);
            a[i][2] = fmaf(xv, wv.z, a[i][2]);
            a[i][3] = fmaf(xv, wv.w, a[i][3]);
        }
    }

    uint2* hp = (uint2*)g_hs;
    #pragma unroll
    for (int i = 0; i < 4; i++) {
        int r = row0 + rg + i;
        if (r < n) {
            float ds = g_dis[r];
            __half2 h01 = __floats2half2_rn(a[i][0] * ds, a[i][1] * ds);
            __half2 h23 = __floats2half2_rn(a[i][2] * ds, a[i][3] * ds);
            hp[(size_t)r * 16 + (c0 >> 2)] = make_uint2(h2_to_u32(h01), h2_to_u32(h23));
        }
    }
}

// ---------------------------------------------------------------------------
// FUSED gather1 + GEMM2: block owns 64 nodes.
// Phase A (8 lanes/node): gather x1 from g_hs, write smem X-tile AND g_x1.
// Phase B: g_hs2 = fp16( dis * (x1tile @ W2) )  — double-buffered, race-free.
__global__ __launch_bounds__(256) void fused_gather1_gemm2_kernel(
    const float* __restrict__ b1, const float* __restrict__ W, int n)
{
    __shared__ float sW[DD * DD];
    __shared__ float sX[DD * DD];

    int t = threadIdx.x;
    int row0 = blockIdx.x * 64;

    {   // W2 into smem
        float4* sW4 = (float4*)sW;
        const float4* W4 = (const float4*)W;
        #pragma unroll
        for (int i = 0; i < 4; i++) sW4[t + i * 256] = W4[t + i * 256];
    }

    // Phase A: 256 threads = 32 nodes x 8 lanes per round, 2 rounds.
    {
        int sub = t >> 3;          // node-within-round (0..31)
        int q8  = t & 7;           // 16B column chunk (0..7)
        #pragma unroll
        for (int rnd = 0; rnd < 2; rnd++) {
            int local = rnd * 32 + sub;      // 0..63
            int d = row0 + local;
            float o[8] = {0.f, 0.f, 0.f, 0.f, 0.f, 0.f, 0.f, 0.f};
            if (d < n) {
                gather_node8(g_hs, d, q8, b1, o);
                float4* xp = (float4*)g_x1 + ((size_t)d * 16 + 2 * q8);
                xp[0] = make_float4(o[0], o[1], o[2], o[3]);
                xp[1] = make_float4(o[4], o[5], o[6], o[7]);
            }
            float* sxp = sX + local * 64 + q8 * 8;
            *(float4*)(sxp)     = make_float4(o[0], o[1], o[2], o[3]);
            *(float4*)(sxp + 4) = make_float4(o[4], o[5], o[6], o[7]);
        }
    }
    __syncthreads();

    // Phase B: GEMM (R10-exact mainloop), writes g_hs2
    int rg = (t >> 4) * 4;
    int c0 = (t & 15) * 4;

    float a[4][4];
    #pragma unroll
    for (int i = 0; i < 4; i++)
        #pragma unroll
        for (int j = 0; j < 4; j++) a[i][j] = 0.f;

    #pragma unroll 16
    for (int k = 0; k < 64; k++) {
        float4 wv = *(const float4*)(sW + k * 64 + c0);
        #pragma unroll
        for (int i = 0; i < 4; i++) {
            float xv = sX[(rg + i) * 64 + k];
            a[i][0] = fmaf(xv, wv.x, a[i][0]);
            a[i][1] = fmaf(xv, wv.y, a[i][1]);
            a[i][2] = fmaf(xv, wv.z, a[i][2]);
            a[i][3] = fmaf(xv, wv.w, a[i][3]);
        }
    }

    uint2* hp = (uint2*)g_hs2;
    #pragma unroll
    for (int i = 0; i < 4; i++) {
        int r = row0 + rg + i;
        if (r < n) {
            float ds = g_dis[r];
            __half2 h01 = __floats2half2_rn(a[i][0] * ds, a[i][1] * ds);
            __half2 h23 = __floats2half2_rn(a[i][2] * ds, a[i][3] * ds);
            hp[(size_t)r * 16 + (c0 >> 2)] = make_uint2(h2_to_u32(h01), h2_to_u32(h23));
        }
    }
}

// ---------------------------------------------------------------------------
// Final gather (layer 2, reads g_hs2) + combine: out = 0.5*(x1 + relu(...)).
// 8 lanes per node.
__global__ __launch_bounds__(256) void gather2_kernel(
    const float* __restrict__ b, float* __restrict__ out, int n)
{
    int gid = blockIdx.x * blockDim.x + threadIdx.x;
    int d = gid >> 3;
    if (d >= n) return;
    int q = gid & 7;

    float o[8];
    gather_node8(g_hs2, d, q, b, o);

    size_t oi = (size_t)d * 16 + 2 * q;
    float4 x1a = ((const float4*)g_x1)[oi];
    float4 x1b = ((const float4*)g_x1)[oi + 1];
    float4 r0 = make_float4(0.5f * (x1a.x + o[0]), 0.5f * (x1a.y + o[1]),
                            0.5f * (x1a.z + o[2]), 0.5f * (x1a.w + o[3]));
    float4 r1 = make_float4(0.5f * (x1b.x + o[4]), 0.5f * (x1b.y + o[5]),
                            0.5f * (x1b.z + o[6]), 0.5f * (x1b.w + o[7]));
    ((float4*)out)[oi]     = r0;
    ((float4*)out)[oi + 1] = r1;
}

// ---------------------------------------------------------------------------
extern "C" void kernel_launch(void* const* d_in, const int* in_sizes, int n_in,
                              void* d_out, int out_size) {
    const float* x  = (const float*)d_in[0];
    const int*   ei = (const int*)d_in[1];      // int32 (JAX default x64-disabled)
    const float* ew = (const float*)d_in[2];
    const float* W1 = (const float*)d_in[3];
    const float* b1 = (const float*)d_in[4];
    const float* W2 = (const float*)d_in[5];
    const float* b2 = (const float*)d_in[6];
    float* out = (float*)d_out;

    int n = in_sizes[0] / DD;      // 100000
    int E = in_sizes[2];           // 1200000

    int nb_n    = (n + 255) / 256;
    int nb_e    = (E + 255) / 256;
    int nb_gat8 = (int)(((long long)n * 8 + 255) / 256);
    int nb_g    = (n + 63) / 64;

    // CSR + degree (shared across both layers) — serial single-stream chain
    init_kernel<<<nb_n, 256>>>(n);
    count_kernel<<<nb_e, 256>>>(ei, ew, E);
    scan_dis_kernel<<<1, 1024>>>(n);               // scan + dis fused
    fill_kernel<<<nb_e, 256>>>(ei, ew, E);

    // Layer 1 GEMM
    gemm_hs_kernel<<<nb_g, 256>>>(x, W1, n);
    // gather1 + GEMM2 fused (race-free: reads g_hs, writes g_hs2)
    fused_gather1_gemm2_kernel<<<nb_g, 256>>>(b1, W2, n);
    // Layer 2 gather + combine (reads g_hs2)
    gather2_kernel<<<nb_gat8, 256>>>(b2, out, n);
}